// round 17
// baseline (speedup 1.0000x reference)
#include <cuda_runtime.h>
#include <cuda_fp16.h>
#include <cstdint>

// out = concat(adj_t @ x, adj_t2 @ x), N=8192, D=256, fp32.
// R17: warp-specialized. 8 consumer warps (one matrix each, 64Mx64N,
// fp16 frags only) + 2 producer warps that LDG fp32 A -> cvt -> STS fp16.
// Producer threads carry no accumulators, so the fp16-A conversion no
// longer fights the consumers' 128 acc registers. B: one shared copy via
// consumer cp.async. Named-barrier FULL/EMPTY handshake, 2 stages.

constexpr int NN = 8192;
constexpr int DD = 256;
constexpr int BM = 64;
constexpr int BK = 64;
constexpr int NITER = NN / BK;        // 128
constexpr int ASH = 72;               // halves per A row (CF frag LDS)
constexpr int A_MAT = BM * ASH * 2;   // 9216 B per matrix per stage
constexpr int A_ST = 2 * A_MAT;       // 18432
constexpr int BSH = 72;               // halves per B row
constexpr int B_ST = DD * BSH * 2;    // 36864
constexpr int B_OFF = A_ST;
constexpr int STG = A_ST + B_ST;      // 55296
constexpr int SMEM_BYTES = 2 * STG;   // 110592

__device__ __half g_xh[(size_t)DD * NN];  // x transposed [n][k], fp16 rn

#define CP_ASYNC16(dst, src) \
    asm volatile("cp.async.cg.shared.global [%0], [%1], 16;" :: "r"(dst), "l"(src))

__device__ __forceinline__ uint32_t smem_u32(const void* p) {
    uint32_t a;
    asm("{ .reg .u64 t; cvta.to.shared.u64 t, %1; cvt.u32.u64 %0, t; }"
        : "=r"(a) : "l"(p));
    return a;
}

__device__ __forceinline__ uint32_t pack_h2(float lo, float hi) {
    uint32_t r;
    asm("cvt.rn.f16x2.f32 %0, %1, %2;" : "=r"(r) : "f"(hi), "f"(lo));
    return r;
}

__device__ __forceinline__ void mma_f16(float c[4], const uint32_t a[4],
                                        const uint32_t b0, const uint32_t b1) {
    asm volatile(
        "mma.sync.aligned.m16n8k16.row.col.f32.f16.f16.f32 "
        "{%0,%1,%2,%3}, {%4,%5,%6,%7}, {%8,%9}, {%0,%1,%2,%3};"
        : "+f"(c[0]), "+f"(c[1]), "+f"(c[2]), "+f"(c[3])
        : "r"(a[0]), "r"(a[1]), "r"(a[2]), "r"(a[3]), "r"(b0), "r"(b1));
}

// ---------------- prep: x -> fp16(rn), transposed to [DD][NN] ----------------
__global__ void xprep(const float* __restrict__ x) {
    __shared__ float tile[32][33];
    const int kb = blockIdx.x * 32;
    const int nb = blockIdx.y * 32;
    const int tx = threadIdx.x;
    const int ty = threadIdx.y;   // blockDim (32, 8)
#pragma unroll
    for (int j = 0; j < 32; j += 8)
        tile[ty + j][tx] = x[(size_t)(kb + ty + j) * DD + nb + tx];
    __syncthreads();
#pragma unroll
    for (int j = 0; j < 32; j += 8)
        g_xh[(size_t)(nb + ty + j) * NN + kb + tx] = __float2half_rn(tile[tx][ty + j]);
}

// ---------------- fused GEMM: producer/consumer warp specialization --------
__global__ void __launch_bounds__(320, 1) h2gcn_mma(
    const float* __restrict__ adj1,
    const float* __restrict__ adj2,
    float* __restrict__ out)
{
    extern __shared__ char smc[];
    const uint32_t smb = smem_u32(smc);

    const int t    = threadIdx.x;
    const int wid  = t >> 5;
    const int lane = t & 31;
    const int m0   = blockIdx.x * BM;

    if (wid < 8) {
        // ================= CONSUMER =================
        const int g   = wid >> 2;     // matrix (0: adj_t, 1: adj_t2)
        const int wn  = wid & 3;      // warp column (64 N each)
        const int gid = lane >> 2;
        const int tig = lane & 3;
        const int koff = g * 2;       // SMSP buddies (wid, wid+4) anti-phased

        // B cp.async: 2048 chunks / 256 threads = 8 each
        const char* bp = reinterpret_cast<const char*>(
            g_xh + (size_t)(t >> 3) * NN) + (t & 7) * 16;
        const uint32_t bdst0 = (uint32_t)(B_OFF + (t >> 3) * (BSH * 2) + (t & 7) * 16);

        auto load_B = [&](int buf) {
            const uint32_t sb = smb + (uint32_t)(buf * STG);
#pragma unroll
            for (int j = 0; j < 8; j++)
                CP_ASYNC16(sb + bdst0 + j * (32 * BSH * 2), bp + (size_t)j * (32 * NN * 2));
            bp += BK * 2;   // 64 halves forward in k
            asm volatile("cp.async.commit_group;");
        };

        float acc[4][8][4];
#pragma unroll
        for (int mt = 0; mt < 4; mt++)
#pragma unroll
            for (int nt = 0; nt < 8; nt++)
#pragma unroll
                for (int i = 0; i < 4; i++) acc[mt][nt][i] = 0.0f;

        const int abase = gid * ASH + 2 * tig;   // halves within matrix region
        const int bn0   = wn * 64 + gid;

        load_B(0);

        for (int it = 0; it < NITER; it++) {
            const int buf = it & 1;
            // A(it) ready (also syncs consumers among themselves)
            if (buf == 0) asm volatile("bar.sync 1, 320;" ::: "memory");
            else          asm volatile("bar.sync 2, 320;" ::: "memory");

            if (it + 1 < NITER) {
                load_B(buf ^ 1);
                asm volatile("cp.async.wait_group 1;");
            } else {
                asm volatile("cp.async.wait_group 0;");
            }

            const char* stage = smc + buf * STG;
            const __half* sA = reinterpret_cast<const __half*>(stage + g * A_MAT);
            const __half* sB = reinterpret_cast<const __half*>(stage + B_OFF);

#pragma unroll
            for (int ks = 0; ks < 4; ks++) {
                const int k0 = ((ks + koff) & 3) * 16;
                uint32_t b0[8], b1[8];
#pragma unroll
                for (int nt = 0; nt < 8; nt++) {
                    const __half* pb = sB + (size_t)(bn0 + nt * 8) * BSH + k0 + 2 * tig;
                    b0[nt] = *reinterpret_cast<const uint32_t*>(pb);
                    b1[nt] = *reinterpret_cast<const uint32_t*>(pb + 8);
                }
                uint32_t a[4][4];
#pragma unroll
                for (int mt = 0; mt < 4; mt++) {
                    const __half* pa = sA + abase + mt * 16 * ASH + k0;
                    a[mt][0] = *reinterpret_cast<const uint32_t*>(pa);
                    a[mt][1] = *reinterpret_cast<const uint32_t*>(pa + 8 * ASH);
                    a[mt][2] = *reinterpret_cast<const uint32_t*>(pa + 8);
                    a[mt][3] = *reinterpret_cast<const uint32_t*>(pa + 8 * ASH + 8);
                }
#pragma unroll
                for (int mt = 0; mt < 4; mt++)
#pragma unroll
                    for (int nt = 0; nt < 8; nt++)
                        mma_f16(acc[mt][nt], a[mt], b0[nt], b1[nt]);
            }

            // A buffer `buf` free
            if (buf == 0) asm volatile("bar.arrive 3, 320;" ::: "memory");
            else          asm volatile("bar.arrive 4, 320;" ::: "memory");
        }

        // Epilogue: out[8192, 512]; matrix g at column offset g*256
        const int colbase = g * DD + wn * 64 + 2 * tig;
#pragma unroll
        for (int mt = 0; mt < 4; mt++) {
            const int row = m0 + mt * 16 + gid;
#pragma unroll
            for (int nt = 0; nt < 8; nt++) {
                float* p0 = out + (size_t)row * (2 * DD) + colbase + nt * 8;
                float* p1 = p0 + 8 * (2 * DD);
                *reinterpret_cast<float2*>(p0) = make_float2(acc[mt][nt][0], acc[mt][nt][1]);
                *reinterpret_cast<float2*>(p1) = make_float2(acc[mt][nt][2], acc[mt][nt][3]);
            }
        }
    } else {
        // ================= PRODUCER (warps 8, 9) =================
        const int pw = wid - 8;                    // matrix
        const float* adjg = pw ? adj2 : adj1;
        // chunk q = lane + 32*s (s=0..31): row = (lane>>4) + 2s, c = lane&15
        const int rb = lane >> 4;                  // 0 or 1
        const int cc = lane & 15;                  // 16B chunk within 256B row
        const float* ap = adjg + (size_t)(m0 + rb) * NN + cc * 4;
        const uint32_t asts0 = (uint32_t)(pw * A_MAT + rb * (ASH * 2) + cc * 8);

        auto fill = [&](int buf) {
            char* base = smc + buf * STG + asts0;
            float4 va[8], vb[8];
#pragma unroll
            for (int j = 0; j < 8; j++)
                va[j] = *reinterpret_cast<const float4*>(ap + (size_t)(2 * j) * NN);
#pragma unroll
            for (int j = 0; j < 8; j++)
                vb[j] = *reinterpret_cast<const float4*>(ap + (size_t)(2 * (8 + j)) * NN);
#pragma unroll
            for (int j = 0; j < 8; j++) {
                uint2 h; h.x = pack_h2(va[j].x, va[j].y); h.y = pack_h2(va[j].z, va[j].w);
                *reinterpret_cast<uint2*>(base + (size_t)(2 * j) * (ASH * 2)) = h;
            }
#pragma unroll
            for (int j = 0; j < 8; j++)
                va[j] = *reinterpret_cast<const float4*>(ap + (size_t)(2 * (16 + j)) * NN);
#pragma unroll
            for (int j = 0; j < 8; j++) {
                uint2 h; h.x = pack_h2(vb[j].x, vb[j].y); h.y = pack_h2(vb[j].z, vb[j].w);
                *reinterpret_cast<uint2*>(base + (size_t)(2 * (8 + j)) * (ASH * 2)) = h;
            }
#pragma unroll
            for (int j = 0; j < 8; j++)
                vb[j] = *reinterpret_cast<const float4*>(ap + (size_t)(2 * (24 + j)) * NN);
#pragma unroll
            for (int j = 0; j < 8; j++) {
                uint2 h; h.x = pack_h2(va[j].x, va[j].y); h.y = pack_h2(va[j].z, va[j].w);
                *reinterpret_cast<uint2*>(base + (size_t)(2 * (16 + j)) * (ASH * 2)) = h;
            }
#pragma unroll
            for (int j = 0; j < 8; j++) {
                uint2 h; h.x = pack_h2(vb[j].x, vb[j].y); h.y = pack_h2(vb[j].z, vb[j].w);
                *reinterpret_cast<uint2*>(base + (size_t)(2 * (24 + j)) * (ASH * 2)) = h;
            }
            ap += BK;   // advance 64 floats in k
            asm volatile("membar.cta;");
        };

        fill(0);
        asm volatile("bar.arrive 1, 320;" ::: "memory");
        fill(1);
        asm volatile("bar.arrive 2, 320;" ::: "memory");
        for (int it = 2; it < NITER; it++) {
            const int buf = it & 1;
            if (buf == 0) asm volatile("bar.sync 3, 320;" ::: "memory");
            else          asm volatile("bar.sync 4, 320;" ::: "memory");
            fill(buf);
            if (buf == 0) asm volatile("bar.arrive 1, 320;" ::: "memory");
            else          asm volatile("bar.arrive 2, 320;" ::: "memory");
        }
    }
}

extern "C" void kernel_launch(void* const* d_in, const int* in_sizes, int n_in,
                              void* d_out, int out_size) {
    const float* x  = nullptr;
    const float* a1 = nullptr;
    const float* a2 = nullptr;
    for (int i = 0; i < n_in; i++) {
        if (in_sizes[i] == NN * DD)  x  = (const float*)d_in[i];
        else if (!a1)                a1 = (const float*)d_in[i];
        else                         a2 = (const float*)d_in[i];
    }

    static bool attr_set = false;
    if (!attr_set) {
        cudaFuncSetAttribute(h2gcn_mma,
                             cudaFuncAttributeMaxDynamicSharedMemorySize, SMEM_BYTES);
        attr_set = true;
    }

    xprep<<<dim3(NN / 32, DD / 32), dim3(32, 8)>>>(x);
    h2gcn_mma<<<NN / BM, 320, SMEM_BYTES>>>(a1, a2, (float*)d_out);
}